// round 13
// baseline (speedup 1.0000x reference)
#include <cuda_runtime.h>

#define CB 32
#define CT 1024
#define CS 256
#define CN 80

#define NEGF (-3.4028234663852886e38f)   // jnp.finfo(float32).min == -FLT_MAX
#define LOG2PI_F 1.8378770664093453f

// Scratch (global __device__ arrays are the allowed scratch mechanism)
static __device__ float g_ll[(size_t)CB * CT * CS];   // 33.5 MB masked log-likelihood
static __device__ int   g_idx[CB * CT];               // backtracked argmax index per (b,t)

// ---------------------------------------------------------------------------
// Kernel A: ll[b,t,s] = -0.5*(log(2pi) + |lat|^2 - 2*lat.mean + |mean|^2) * mask
// Unchanged from the passing R9 version (64.8us): interleaved conflict-free
// mapping + early exit for fully-masked t-chunks.
// ---------------------------------------------------------------------------
__global__ __launch_bounds__(256, 2)
void kernelA(const float* __restrict__ latent, const float* __restrict__ mean,
             const int* __restrict__ textlen, const int* __restrict__ mellen)
{
    extern __shared__ float sh[];
    float* smean  = sh;                          // [CN][129]
    float* slat   = smean + CN * 129;            // [CN][65]
    float* smean2 = slat + CN * 65;              // [128]
    float* slat2  = smean2 + 128;                // [64]

    const int b   = blockIdx.x >> 5;
    const int rem = blockIdx.x & 31;
    const int tc  = rem >> 1;
    const int sc  = rem & 1;
    const int tid = threadIdx.x;
    const int tbase = tc * 64;
    const int sbase = sc * 128;

    const int ml_b = mellen[b];
    if (tbase >= ml_b) return;    // fully-masked chunk: rows never consumed
    const int tl_b = textlen[b];

    for (int idx = tid; idx < 128 * CN; idx += 256) {
        int sl = idx / CN, n = idx - sl * CN;
        smean[n * 129 + sl] = mean[((size_t)(b * CS + sbase + sl)) * CN + n];
    }
    for (int idx = tid; idx < 64 * CN; idx += 256) {
        int tl = idx / CN, n = idx - tl * CN;
        slat[n * 65 + tl] = latent[((size_t)(b * CT + tbase + tl)) * CN + n];
    }
    __syncthreads();

    if (tid < 128) {
        float acc = 0.f;
        #pragma unroll 4
        for (int n = 0; n < CN; n++) {
            float v = smean[n * 129 + tid];
            acc = __fadd_rn(acc, __fmul_rn(v, v));
        }
        smean2[tid] = acc;
    } else if (tid < 192) {
        int tl = tid - 128;
        float acc = 0.f;
        #pragma unroll 4
        for (int n = 0; n < CN; n++) {
            float v = slat[n * 65 + tl];
            acc = __fadd_rn(acc, __fmul_rn(v, v));
        }
        slat2[tl] = acc;
    }
    __syncthreads();

    const int tx = tid & 15;    // s lane: s_local = tx + 16*i (i<8)
    const int ty = tid >> 4;    // t group: t_local = ty*4 + j (j<4)

    float acc[4][8];
    #pragma unroll
    for (int j = 0; j < 4; j++)
        #pragma unroll
        for (int i = 0; i < 8; i++) acc[j][i] = 0.f;

    const float* mrow = smean + tx;
    const float* arow = slat + ty * 4;

    #pragma unroll 2
    for (int n = 0; n < CN; n++) {
        float a[4], m[8];
        #pragma unroll
        for (int j = 0; j < 4; j++) a[j] = arow[n * 65 + j];
        #pragma unroll
        for (int i = 0; i < 8; i++) m[i] = mrow[n * 129 + 16 * i];
        #pragma unroll
        for (int j = 0; j < 4; j++)
            #pragma unroll
            for (int i = 0; i < 8; i++)
                acc[j][i] = __fmaf_rn(a[j], m[i], acc[j][i]);
    }

    #pragma unroll
    for (int j = 0; j < 4; j++) {
        int tl = ty * 4 + j;
        int tg = tbase + tl;
        float l2 = slat2[tl];
        float rowmask = (tg < ml_b) ? 1.f : 0.f;
        float* outrow = g_ll + ((size_t)(b * CT + tg)) * CS + sbase;
        #pragma unroll
        for (int i = 0; i < 8; i++) {
            int sl = tx + 16 * i;
            float dist = __fadd_rn(__fmaf_rn(-2.f, acc[j][i], l2), smean2[sl]);
            float msk  = (sbase + sl < tl_b) ? rowmask : 0.f;
            float ll   = __fmul_rn(__fmul_rn(-0.5f, __fadd_rn(LOG2PI_F, dist)), msk);
            outrow[sl] = ll;
        }
    }
}

// ---------------------------------------------------------------------------
// Kernel B: Viterbi forward + backtrack. FOUR warps per batch (one block of
// 128 threads), warp w owns s in [64w, 64w+64) as split halves:
// lane L -> s0 = 64w+L, s1 = 64w+32+L. This is the Round-5 dataflow that
// benched rel_err 0.0 — now with depth-8 REGISTER rings (full unroll: no
// local-memory spill) and the mellen forward trim.
// Cross-warp boundary: slot[w][t] = boundary prob ENTERING step t
// (slot[w][0]=0 initial state; producer lane31 writes slot[w][t+1] after its
// step-t update; +1.0f sentinel = not ready, all real probs <= 0).
// Warp w+1's per-step inputs don't depend on warp w's same-step output, so
// the pipeline's steady rate = one warp's step rate (~18 instr/step on its
// own SMSP) instead of the single-warp version's ~48.
// ---------------------------------------------------------------------------
__global__ __launch_bounds__(128, 1)
void kernelB(const int* __restrict__ textlen, const int* __restrict__ mellen)
{
    __shared__ unsigned sdir[CT][8];          // [t][s>>5]: dir bits (1 = stay), 32KB
    __shared__ volatile float slot[3][CT];    // [w][t]: boundary prob entering step t

    const int b   = blockIdx.x;
    const int tid = threadIdx.x;
    const int w   = tid >> 5;
    const int L   = tid & 31;
    const int tl_b = textlen[b];
    const int ml_b = mellen[b];

    // init sentinels; slot[w][0] = initial DP state (zeros)
    for (int i = tid; i < 3 * CT; i += 128)
        ((volatile float*)slot)[i] = 1.0f;
    if (tid < 3) slot[tid][0] = 0.0f;
    __syncthreads();

    const float* __restrict__ llb = g_ll + (size_t)b * CT * CS + w * 64 + L;
    const int s0 = w * 64 + L;
    const int s1 = s0 + 32;

    float p0 = 0.f, p1 = 0.f;

    // depth-8 register ring; slot index always a literal (full unroll)
    float r0[8], r1[8];
    #pragma unroll
    for (int r = 0; r < 8; r++) {
        r0[r] = llb[r * CS];
        r1[r] = llb[r * CS + 32];
    }

#define BSTEP(T, U, MASKED)                                                   \
    {                                                                         \
        const int t_ = (T);                                                   \
        float ll0 = r0[U], ll1 = r1[U];                                       \
        int tp_ = t_ + 8;                                                     \
        if (tp_ < CT) {                                                       \
            r0[U] = llb[tp_ * CS];                                            \
            r1[U] = llb[tp_ * CS + 32];                                       \
        }                                                                     \
        float bnd = NEGF;                                                     \
        if (w > 0) { do { bnd = slot[w - 1][t_]; } while (bnd > 0.5f); }      \
        float prev0 = __shfl_up_sync(0xffffffffu, p0, 1);                     \
        float prev1 = __shfl_up_sync(0xffffffffu, p1, 1);                     \
        float p0top = __shfl_sync(0xffffffffu, p0, 31);                       \
        if (L == 0) { prev0 = bnd; prev1 = p0top; }                           \
        bool mk0 = (p0 >= prev0);                                             \
        bool mk1 = (p1 >= prev1);                                             \
        float n0 = __fadd_rn(fmaxf(p0, prev0), ll0);                          \
        float n1 = __fadd_rn(fmaxf(p1, prev1), ll1);                          \
        if (MASKED) {                                                         \
            p0 = (s0 <= t_) ? n0 : NEGF;                                      \
            p1 = (s1 <= t_) ? n1 : NEGF;                                      \
        } else { p0 = n0; p1 = n1; }                                          \
        unsigned bb0 = __ballot_sync(0xffffffffu, mk0);                       \
        unsigned bb1 = __ballot_sync(0xffffffffu, mk1);                       \
        if (L == 0) { sdir[t_][2 * w] = bb0; sdir[t_][2 * w + 1] = bb1; }     \
        if (L == 31 && w < 3 && t_ + 1 < CT) slot[w][t_ + 1] = p1;            \
    }

    for (int t0 = 0; t0 < 256; t0 += 8) {
        BSTEP(t0 + 0, 0, true) BSTEP(t0 + 1, 1, true)
        BSTEP(t0 + 2, 2, true) BSTEP(t0 + 3, 3, true)
        BSTEP(t0 + 4, 4, true) BSTEP(t0 + 5, 5, true)
        BSTEP(t0 + 6, 6, true) BSTEP(t0 + 7, 7, true)
    }
    for (int t0 = 256; t0 < ml_b; t0 += 8) {     // rows >= mellen are masked:
        BSTEP(t0 + 0, 0, false) BSTEP(t0 + 1, 1, false)  // dir forced 1, idx
        BSTEP(t0 + 2, 2, false) BSTEP(t0 + 3, 3, false)  // pinned in backtrack
        BSTEP(t0 + 4, 4, false) BSTEP(t0 + 5, 5, false)
        BSTEP(t0 + 6, 6, false) BSTEP(t0 + 7, 7, false)
    }
#undef BSTEP

    __syncthreads();

    // Backtrack (Round-5-verified word version). Reference forces dir=1
    // wherever attnmask==0, so for t >= mellen the index stays pinned at
    // textlen-1; inside the mask the traced path never enters s >= textlen.
    // De-chained in groups of 4 rows: index span <= 4 => 2 candidate words.
    if (tid == 0) {
        int* gout = g_idx + b * CT;
        int idx = tl_b - 1;
        int t = CT - 1;
        for (; t >= ml_b; --t) gout[t] = idx;
        while (t >= 3) {
            int A  = idx >> 5;
            int Bw = ((idx >= 3) ? (idx - 3) : 0) >> 5;
            unsigned hi0 = sdir[t][A];
            unsigned hi1 = sdir[t - 1][A], lo1 = sdir[t - 1][Bw];
            unsigned hi2 = sdir[t - 2][A], lo2 = sdir[t - 2][Bw];
            unsigned hi3 = sdir[t - 3][A], lo3 = sdir[t - 3][Bw];
            gout[t] = idx;
            idx += (int)((hi0 >> (idx & 31)) & 1u) - 1;
            gout[t - 1] = idx;
            unsigned wd = ((idx >> 5) == A) ? hi1 : lo1;
            idx += (int)((wd >> (idx & 31)) & 1u) - 1;
            gout[t - 2] = idx;
            wd = ((idx >> 5) == A) ? hi2 : lo2;
            idx += (int)((wd >> (idx & 31)) & 1u) - 1;
            gout[t - 3] = idx;
            wd = ((idx >> 5) == A) ? hi3 : lo3;
            idx += (int)((wd >> (idx & 31)) & 1u) - 1;
            t -= 4;
        }
        for (; t >= 0; --t) {
            gout[t] = idx;
            idx += (int)((sdir[t][idx >> 5] >> (idx & 31)) & 1u) - 1;
        }
    }
}

// ---------------------------------------------------------------------------
// Kernel C: write residual [B,T,N] then attn [B,T,S] into d_out (float4).
// Unchanged from the passing R9 version.
// ---------------------------------------------------------------------------
__global__ __launch_bounds__(256)
void kernelC(const float* __restrict__ latent, const float* __restrict__ mean,
             const int* __restrict__ mellen, float* __restrict__ out)
{
    const int RES4 = CB * CT * CN / 4;           // 655360
    const int TOT4 = RES4 + CB * CT * CS / 4;    // 2752512
    int i = blockIdx.x * blockDim.x + threadIdx.x;
    if (i >= TOT4) return;
    float4* out4 = (float4*)out;

    if (i < RES4) {
        int f  = i << 2;
        int bt = f / CN;
        int n  = f - bt * CN;
        int b  = bt >> 10;
        int t  = bt & (CT - 1);
        float4 r = ((const float4*)latent)[i];
        if (t < __ldg(&mellen[b])) {
            int sidx = g_idx[bt];
            float4 mv = *(const float4*)(mean + ((size_t)(b * CS + sidx)) * CN + n);
            r.x -= mv.x; r.y -= mv.y; r.z -= mv.z; r.w -= mv.w;
        }
        out4[i] = r;
    } else {
        int f  = (i - RES4) << 2;
        int bt = f >> 8;                 // / CS
        int s0 = f & (CS - 1);
        int b  = bt >> 10;
        int t  = bt & (CT - 1);
        float4 v = make_float4(0.f, 0.f, 0.f, 0.f);
        if (t < __ldg(&mellen[b])) {
            int sidx = g_idx[bt];        // always < textlen[b] => textmask == 1
            v.x = (sidx == s0)     ? 1.f : 0.f;
            v.y = (sidx == s0 + 1) ? 1.f : 0.f;
            v.z = (sidx == s0 + 2) ? 1.f : 0.f;
            v.w = (sidx == s0 + 3) ? 1.f : 0.f;
        }
        out4[i] = v;
    }
}

extern "C" void kernel_launch(void* const* d_in, const int* in_sizes, int n_in,
                              void* d_out, int out_size)
{
    const float* latent  = (const float*)d_in[0];   // [32,1024,80]
    const float* mean    = (const float*)d_in[1];   // [32,256,80]
    const int*   textlen = (const int*)d_in[2];     // [32]
    const int*   mellen  = (const int*)d_in[3];     // [32]
    float* out = (float*)d_out;                     // residual (B*T*N) ++ attn (B*T*S)

    const size_t shA = (size_t)(CN * 129 + CN * 65 + 128 + 64) * sizeof(float);
    cudaFuncSetAttribute(kernelA, cudaFuncAttributeMaxDynamicSharedMemorySize, (int)shA);

    kernelA<<<CB * 32, 256, shA>>>(latent, mean, textlen, mellen);
    kernelB<<<CB, 128>>>(textlen, mellen);

    const int TOT4 = (CB * CT * CN + CB * CT * CS) / 4;
    kernelC<<<(TOT4 + 255) / 256, 256>>>(latent, mean, mellen, out);
}

// round 14
// speedup vs baseline: 1.8617x; 1.8617x over previous
#include <cuda_runtime.h>

#define CB 32
#define CT 1024
#define CS 256
#define CN 80

#define NEGF (-3.4028234663852886e38f)   // jnp.finfo(float32).min == -FLT_MAX
#define LOG2PI_F 1.8378770664093453f

// Scratch (global __device__ arrays are the allowed scratch mechanism)
static __device__ float g_ll[(size_t)CB * CT * CS];   // 33.5 MB masked log-likelihood
static __device__ int   g_idx[CB * CT];               // backtracked argmax index per (b,t)
static __device__ int   g_flag[CB * 16];              // per-(b,tc) chunk-ready counters
                                                      // (zero at load; kernelC re-zeroes)

// ---------------------------------------------------------------------------
// Fused kernel A+B (R11 structure, rel_err 0.0 at 149.5us).
//   blocks 0..31     : B role — Viterbi forward + backtrack, ONE warp/batch.
//     R14 change: the worker is WARP 7 (tid 224..255), not warp 0. The SMSP
//     arbiter is highest-wid-first; as wid 0 the serial DP warp was outranked
//     by every co-resident A warp (wid 1..7) and got only leftover issue
//     slots (~1.85x slowdown). As wid 7 it ties/beats them.
//   blocks 32..1055  : A role — 64t x 128s ll tiles, chunk-major order
//                      (i = cc*32 + b) so every batch's chunk 0 lands in wave 1.
// Per-element arithmetic identical to the rel_err=0.0 R9/R11 kernels.
// ---------------------------------------------------------------------------
__global__ __launch_bounds__(256, 2)
void kernelAB(const float* __restrict__ latent, const float* __restrict__ mean,
              const int* __restrict__ textlen, const int* __restrict__ mellen)
{
    extern __shared__ float sh[];

    if (blockIdx.x >= 32) {
        // ================= A role: ll producer =================
        float* smean  = sh;                          // [CN][129]
        float* slat   = smean + CN * 129;            // [CN][65]
        float* smean2 = slat + CN * 65;              // [128]
        float* slat2  = smean2 + 128;                // [64]

        const int i   = blockIdx.x - 32;
        const int b   = i & 31;
        const int cc  = i >> 5;          // chunk-major: all batches' chunk cc together
        const int tc  = cc >> 1;
        const int sc  = cc & 1;
        const int tid = threadIdx.x;
        const int tbase = tc * 64;
        const int sbase = sc * 128;

        const int ml_b = mellen[b];
        if (tbase >= ml_b) {             // fully-masked chunk: rows never consumed,
            if (tid == 0) atomicAdd(&g_flag[b * 16 + tc], 1);   // but must signal
            return;
        }
        const int tl_b = textlen[b];

        for (int idx = tid; idx < 128 * CN; idx += 256) {
            int sl = idx / CN, n = idx - sl * CN;
            smean[n * 129 + sl] = mean[((size_t)(b * CS + sbase + sl)) * CN + n];
        }
        for (int idx = tid; idx < 64 * CN; idx += 256) {
            int tl = idx / CN, n = idx - tl * CN;
            slat[n * 65 + tl] = latent[((size_t)(b * CT + tbase + tl)) * CN + n];
        }
        __syncthreads();

        if (tid < 128) {
            float acc = 0.f;
            #pragma unroll 4
            for (int n = 0; n < CN; n++) {
                float v = smean[n * 129 + tid];
                acc = __fadd_rn(acc, __fmul_rn(v, v));
            }
            smean2[tid] = acc;
        } else if (tid < 192) {
            int tl = tid - 128;
            float acc = 0.f;
            #pragma unroll 4
            for (int n = 0; n < CN; n++) {
                float v = slat[n * 65 + tl];
                acc = __fadd_rn(acc, __fmul_rn(v, v));
            }
            slat2[tl] = acc;
        }
        __syncthreads();

        const int tx = tid & 15;    // s lane: s_local = tx + 16*i2 (i2<8)
        const int ty = tid >> 4;    // t group: t_local = ty*4 + j (j<4)

        float acc[4][8];
        #pragma unroll
        for (int j = 0; j < 4; j++)
            #pragma unroll
            for (int i2 = 0; i2 < 8; i2++) acc[j][i2] = 0.f;

        const float* mrow = smean + tx;
        const float* arow = slat + ty * 4;

        #pragma unroll 2
        for (int n = 0; n < CN; n++) {
            float a[4], m[8];
            #pragma unroll
            for (int j = 0; j < 4; j++) a[j] = arow[n * 65 + j];
            #pragma unroll
            for (int i2 = 0; i2 < 8; i2++) m[i2] = mrow[n * 129 + 16 * i2];
            #pragma unroll
            for (int j = 0; j < 4; j++)
                #pragma unroll
                for (int i2 = 0; i2 < 8; i2++)
                    acc[j][i2] = __fmaf_rn(a[j], m[i2], acc[j][i2]);
        }

        #pragma unroll
        for (int j = 0; j < 4; j++) {
            int tl = ty * 4 + j;
            int tg = tbase + tl;
            float l2 = slat2[tl];
            float rowmask = (tg < ml_b) ? 1.f : 0.f;
            float* outrow = g_ll + ((size_t)(b * CT + tg)) * CS + sbase;
            #pragma unroll
            for (int i2 = 0; i2 < 8; i2++) {
                int sl = tx + 16 * i2;
                float dist = __fadd_rn(__fmaf_rn(-2.f, acc[j][i2], l2), smean2[sl]);
                float msk  = (sbase + sl < tl_b) ? rowmask : 0.f;
                float ll   = __fmul_rn(__fmul_rn(-0.5f, __fadd_rn(LOG2PI_F, dist)), msk);
                outrow[sl] = ll;
            }
        }

        // signal chunk ready (canonical: stores -> fence -> bar -> one atomic)
        __threadfence();
        __syncthreads();
        if (tid == 0) atomicAdd(&g_flag[b * 16 + tc], 1);
        return;
    }

    // ================= B role: Viterbi consumer =================
    if ((threadIdx.x >> 5) != 7) return;   // worker = WARP 7 (arbiter priority)
    unsigned char* sdir = (unsigned char*)sh;   // [CT*32]: dir bits, 1 = stay

    const int b = blockIdx.x;
    const int L = threadIdx.x & 31;
    const int tl_b = textlen[b];
    const int ml_b = mellen[b];

    const float4* __restrict__ base = (const float4*)(g_ll + (size_t)b * CT * CS);
    const int roff = L * 2;   // float4 index: lane L covers s = 8L..8L+7

    const int* fl = g_flag + b * 16;
    int ready = 0;            // chunks confirmed ready (both s-halves)

#define WAITCH(CN_)                                                           \
    {                                                                         \
        int cw_ = (CN_);                                                      \
        if (ready <= cw_) {                                                   \
            while (ready <= cw_) {                                            \
                if (*(volatile int*)(fl + ready) >= 2) ready++;               \
            }                                                                 \
            __threadfence();                                                  \
        }                                                                     \
        asm volatile("" ::: "memory");                                        \
    }

    float p[8];
    #pragma unroll
    for (int k = 0; k < 8; k++) p[k] = 0.f;

    WAITCH(0)
    // 8-deep register ring (ring slot == unroll position -> compile-time index)
    float4 bufA[8], bufB[8];
    #pragma unroll
    for (int r = 0; r < 8; r++) {
        bufA[r] = base[r * (CS / 4) + roff];
        bufB[r] = base[r * (CS / 4) + roff + 1];
    }

#define BSTEP(T, U, MASKED)                                                   \
    {                                                                         \
        const int t_ = (T);                                                   \
        float4 lo = bufA[U], hi = bufB[U];                                    \
        int tp_ = t_ + 8;                                                     \
        if (tp_ < CT) {                                                       \
            bufA[U] = base[tp_ * (CS / 4) + roff];                            \
            bufB[U] = base[tp_ * (CS / 4) + roff + 1];                        \
        }                                                                     \
        float llv[8] = {lo.x, lo.y, lo.z, lo.w, hi.x, hi.y, hi.z, hi.w};      \
        float prevv = __shfl_up_sync(0xffffffffu, p[7], 1);                   \
        if (L == 0) prevv = NEGF;                                             \
        unsigned bits = 0;                                                    \
        _Pragma("unroll")                                                     \
        for (int k = 0; k < 8; k++) {                                         \
            float cur = p[k];                                                 \
            bits |= (cur >= prevv ? 1u : 0u) << k;                            \
            float m  = fmaxf(cur, prevv);                                     \
            float nn = __fadd_rn(m, llv[k]);                                  \
            p[k] = MASKED ? ((((L << 3) + k) <= t_) ? nn : NEGF) : nn;        \
            prevv = cur;                                                      \
        }                                                                     \
        sdir[t_ * 32 + L] = (unsigned char)bits;                              \
    }

    for (int t0 = 0; t0 < 256; t0 += 8) {
        int cn = (t0 + 15) >> 6;
        WAITCH(cn)
        BSTEP(t0 + 0, 0, true) BSTEP(t0 + 1, 1, true)
        BSTEP(t0 + 2, 2, true) BSTEP(t0 + 3, 3, true)
        BSTEP(t0 + 4, 4, true) BSTEP(t0 + 5, 5, true)
        BSTEP(t0 + 6, 6, true) BSTEP(t0 + 7, 7, true)
    }
    for (int t0 = 256; t0 < ml_b; t0 += 8) {     // rows >= mellen are masked
        int cn = (t0 + 15) >> 6; if (cn > 15) cn = 15;
        WAITCH(cn)
        BSTEP(t0 + 0, 0, false) BSTEP(t0 + 1, 1, false)
        BSTEP(t0 + 2, 2, false) BSTEP(t0 + 3, 3, false)
        BSTEP(t0 + 4, 4, false) BSTEP(t0 + 5, 5, false)
        BSTEP(t0 + 6, 6, false) BSTEP(t0 + 7, 7, false)
    }
#undef BSTEP
#undef WAITCH

    __syncwarp();

    // Backtrack. Reference forces dir=1 wherever attnmask==0, so for
    // t >= mellen the index stays pinned at textlen-1; inside the mask the
    // traced path never enters s >= textlen, so raw mk bits are correct.
    // De-chained in groups of 4 rows: index span <= 4 => 2 candidate bytes.
    if (L == 0) {
        int* gout = g_idx + b * CT;
        int idx = tl_b - 1;
        int t = CT - 1;
        for (; t >= ml_b; --t) gout[t] = idx;
        while (t >= 3) {
            int A  = idx >> 3;
            int Bq = ((idx >= 3) ? (idx - 3) : 0) >> 3;
            unsigned hi0 = sdir[t * 32 + A];
            unsigned hi1 = sdir[(t - 1) * 32 + A], lo1 = sdir[(t - 1) * 32 + Bq];
            unsigned hi2 = sdir[(t - 2) * 32 + A], lo2 = sdir[(t - 2) * 32 + Bq];
            unsigned hi3 = sdir[(t - 3) * 32 + A], lo3 = sdir[(t - 3) * 32 + Bq];
            gout[t] = idx;
            idx += (int)((hi0 >> (idx & 7)) & 1u) - 1;
            gout[t - 1] = idx;
            unsigned wd = ((idx >> 3) == A) ? hi1 : lo1;
            idx += (int)((wd >> (idx & 7)) & 1u) - 1;
            gout[t - 2] = idx;
            wd = ((idx >> 3) == A) ? hi2 : lo2;
            idx += (int)((wd >> (idx & 7)) & 1u) - 1;
            gout[t - 3] = idx;
            wd = ((idx >> 3) == A) ? hi3 : lo3;
            idx += (int)((wd >> (idx & 7)) & 1u) - 1;
            t -= 4;
        }
        for (; t >= 0; --t) {
            gout[t] = idx;
            idx += (int)((sdir[t * 32 + (idx >> 3)] >> (idx & 7)) & 1u) - 1;
        }
    }
}

// ---------------------------------------------------------------------------
// Kernel C: write residual [B,T,N] then attn [B,T,S] into d_out (float4).
// Also re-zeroes g_flag for the NEXT launch (stream-ordered after all flag
// use; flags are zero-initialized at module load for the first call).
// ---------------------------------------------------------------------------
__global__ __launch_bounds__(256)
void kernelC(const float* __restrict__ latent, const float* __restrict__ mean,
             const int* __restrict__ mellen, float* __restrict__ out)
{
    if (blockIdx.x == 0 && threadIdx.x < CB * 16)
        g_flag[threadIdx.x] = 0;

    const int RES4 = CB * CT * CN / 4;           // 655360
    const int TOT4 = RES4 + CB * CT * CS / 4;    // 2752512
    int i = blockIdx.x * blockDim.x + threadIdx.x;
    if (i >= TOT4) return;
    float4* out4 = (float4*)out;

    if (i < RES4) {
        int f  = i << 2;
        int bt = f / CN;
        int n  = f - bt * CN;
        int b  = bt >> 10;
        int t  = bt & (CT - 1);
        float4 r = ((const float4*)latent)[i];
        if (t < __ldg(&mellen[b])) {
            int sidx = g_idx[bt];
            float4 mv = *(const float4*)(mean + ((size_t)(b * CS + sidx)) * CN + n);
            r.x -= mv.x; r.y -= mv.y; r.z -= mv.z; r.w -= mv.w;
        }
        out4[i] = r;
    } else {
        int f  = (i - RES4) << 2;
        int bt = f >> 8;                 // / CS
        int s0 = f & (CS - 1);
        int b  = bt >> 10;
        int t  = bt & (CT - 1);
        float4 v = make_float4(0.f, 0.f, 0.f, 0.f);
        if (t < __ldg(&mellen[b])) {
            int sidx = g_idx[bt];        // always < textlen[b] => textmask == 1
            v.x = (sidx == s0)     ? 1.f : 0.f;
            v.y = (sidx == s0 + 1) ? 1.f : 0.f;
            v.z = (sidx == s0 + 2) ? 1.f : 0.f;
            v.w = (sidx == s0 + 3) ? 1.f : 0.f;
        }
        out4[i] = v;
    }
}

extern "C" void kernel_launch(void* const* d_in, const int* in_sizes, int n_in,
                              void* d_out, int out_size)
{
    const float* latent  = (const float*)d_in[0];   // [32,1024,80]
    const float* mean    = (const float*)d_in[1];   // [32,256,80]
    const int*   textlen = (const int*)d_in[2];     // [32]
    const int*   mellen  = (const int*)d_in[3];     // [32]
    float* out = (float*)d_out;                     // residual (B*T*N) ++ attn (B*T*S)

    const size_t shA = (size_t)(CN * 129 + CN * 65 + 128 + 64) * sizeof(float);
    cudaFuncSetAttribute(kernelAB, cudaFuncAttributeMaxDynamicSharedMemorySize, (int)shA);

    kernelAB<<<32 + CB * 32, 256, shA>>>(latent, mean, textlen, mellen);

    const int TOT4 = (CB * CT * CN + CB * CT * CS) / 4;
    kernelC<<<(TOT4 + 255) / 256, 256>>>(latent, mean, mellen, out);
}

// round 15
// speedup vs baseline: 1.8637x; 1.0011x over previous
#include <cuda_runtime.h>

#define CB 32
#define CT 1024
#define CS 256
#define CN 80

#define NEGF (-3.4028234663852886e38f)   // jnp.finfo(float32).min == -FLT_MAX
#define LOG2PI_F 1.8378770664093453f

// Scratch (global __device__ arrays are the allowed scratch mechanism)
static __device__ float g_ll[(size_t)CB * CT * CS];   // 33.5 MB masked log-likelihood
static __device__ int   g_idx[CB * CT];               // backtracked argmax index per (b,t)
static __device__ int   g_flag[CB * 16];              // per-(b,tc) chunk-ready counters
                                                      // (zero at load; kernelC re-zeroes)

// ---------------------------------------------------------------------------
// Fused kernel A+B (R11 structure, rel_err 0.0 at 149.5us).
//   blocks 0..31     : B role — Viterbi forward + backtrack, ONE warp/batch.
//     R14 change: the worker is WARP 7 (tid 224..255), not warp 0. The SMSP
//     arbiter is highest-wid-first; as wid 0 the serial DP warp was outranked
//     by every co-resident A warp (wid 1..7) and got only leftover issue
//     slots (~1.85x slowdown). As wid 7 it ties/beats them.
//   blocks 32..1055  : A role — 64t x 128s ll tiles, chunk-major order
//                      (i = cc*32 + b) so every batch's chunk 0 lands in wave 1.
// Per-element arithmetic identical to the rel_err=0.0 R9/R11 kernels.
// ---------------------------------------------------------------------------
__global__ __launch_bounds__(256, 2)
void kernelAB(const float* __restrict__ latent, const float* __restrict__ mean,
              const int* __restrict__ textlen, const int* __restrict__ mellen)
{
    extern __shared__ float sh[];

    if (blockIdx.x >= 32) {
        // ================= A role: ll producer =================
        float* smean  = sh;                          // [CN][129]
        float* slat   = smean + CN * 129;            // [CN][65]
        float* smean2 = slat + CN * 65;              // [128]
        float* slat2  = smean2 + 128;                // [64]

        const int i   = blockIdx.x - 32;
        const int b   = i & 31;
        const int cc  = i >> 5;          // chunk-major: all batches' chunk cc together
        const int tc  = cc >> 1;
        const int sc  = cc & 1;
        const int tid = threadIdx.x;
        const int tbase = tc * 64;
        const int sbase = sc * 128;

        const int ml_b = mellen[b];
        if (tbase >= ml_b) {             // fully-masked chunk: rows never consumed,
            if (tid == 0) atomicAdd(&g_flag[b * 16 + tc], 1);   // but must signal
            return;
        }
        const int tl_b = textlen[b];

        for (int idx = tid; idx < 128 * CN; idx += 256) {
            int sl = idx / CN, n = idx - sl * CN;
            smean[n * 129 + sl] = mean[((size_t)(b * CS + sbase + sl)) * CN + n];
        }
        for (int idx = tid; idx < 64 * CN; idx += 256) {
            int tl = idx / CN, n = idx - tl * CN;
            slat[n * 65 + tl] = latent[((size_t)(b * CT + tbase + tl)) * CN + n];
        }
        __syncthreads();

        if (tid < 128) {
            float acc = 0.f;
            #pragma unroll 4
            for (int n = 0; n < CN; n++) {
                float v = smean[n * 129 + tid];
                acc = __fadd_rn(acc, __fmul_rn(v, v));
            }
            smean2[tid] = acc;
        } else if (tid < 192) {
            int tl = tid - 128;
            float acc = 0.f;
            #pragma unroll 4
            for (int n = 0; n < CN; n++) {
                float v = slat[n * 65 + tl];
                acc = __fadd_rn(acc, __fmul_rn(v, v));
            }
            slat2[tl] = acc;
        }
        __syncthreads();

        const int tx = tid & 15;    // s lane: s_local = tx + 16*i2 (i2<8)
        const int ty = tid >> 4;    // t group: t_local = ty*4 + j (j<4)

        float acc[4][8];
        #pragma unroll
        for (int j = 0; j < 4; j++)
            #pragma unroll
            for (int i2 = 0; i2 < 8; i2++) acc[j][i2] = 0.f;

        const float* mrow = smean + tx;
        const float* arow = slat + ty * 4;

        #pragma unroll 2
        for (int n = 0; n < CN; n++) {
            float a[4], m[8];
            #pragma unroll
            for (int j = 0; j < 4; j++) a[j] = arow[n * 65 + j];
            #pragma unroll
            for (int i2 = 0; i2 < 8; i2++) m[i2] = mrow[n * 129 + 16 * i2];
            #pragma unroll
            for (int j = 0; j < 4; j++)
                #pragma unroll
                for (int i2 = 0; i2 < 8; i2++)
                    acc[j][i2] = __fmaf_rn(a[j], m[i2], acc[j][i2]);
        }

        #pragma unroll
        for (int j = 0; j < 4; j++) {
            int tl = ty * 4 + j;
            int tg = tbase + tl;
            float l2 = slat2[tl];
            float rowmask = (tg < ml_b) ? 1.f : 0.f;
            float* outrow = g_ll + ((size_t)(b * CT + tg)) * CS + sbase;
            #pragma unroll
            for (int i2 = 0; i2 < 8; i2++) {
                int sl = tx + 16 * i2;
                float dist = __fadd_rn(__fmaf_rn(-2.f, acc[j][i2], l2), smean2[sl]);
                float msk  = (sbase + sl < tl_b) ? rowmask : 0.f;
                float ll   = __fmul_rn(__fmul_rn(-0.5f, __fadd_rn(LOG2PI_F, dist)), msk);
                outrow[sl] = ll;
            }
        }

        // signal chunk ready (canonical: stores -> fence -> bar -> one atomic)
        __threadfence();
        __syncthreads();
        if (tid == 0) atomicAdd(&g_flag[b * 16 + tc], 1);
        return;
    }

    // ================= B role: Viterbi consumer =================
    if ((threadIdx.x >> 5) != 7) return;   // worker = WARP 7 (arbiter priority)
    unsigned char* sdir = (unsigned char*)sh;   // [CT*32]: dir bits, 1 = stay

    const int b = blockIdx.x;
    const int L = threadIdx.x & 31;
    const int tl_b = textlen[b];
    const int ml_b = mellen[b];

    const float4* __restrict__ base = (const float4*)(g_ll + (size_t)b * CT * CS);
    const int roff = L * 2;   // float4 index: lane L covers s = 8L..8L+7

    const int* fl = g_flag + b * 16;
    int ready = 0;            // chunks confirmed ready (both s-halves)

#define WAITCH(CN_)                                                           \
    {                                                                         \
        int cw_ = (CN_);                                                      \
        if (ready <= cw_) {                                                   \
            while (ready <= cw_) {                                            \
                if (*(volatile int*)(fl + ready) >= 2) ready++;               \
            }                                                                 \
            __threadfence();                                                  \
        }                                                                     \
        asm volatile("" ::: "memory");                                        \
    }

    float p[8];
    #pragma unroll
    for (int k = 0; k < 8; k++) p[k] = 0.f;

    WAITCH(0)
    // 8-deep register ring (ring slot == unroll position -> compile-time index)
    float4 bufA[8], bufB[8];
    #pragma unroll
    for (int r = 0; r < 8; r++) {
        bufA[r] = base[r * (CS / 4) + roff];
        bufB[r] = base[r * (CS / 4) + roff + 1];
    }

#define BSTEP(T, U, MASKED)                                                   \
    {                                                                         \
        const int t_ = (T);                                                   \
        float4 lo = bufA[U], hi = bufB[U];                                    \
        int tp_ = t_ + 8;                                                     \
        if (tp_ < CT) {                                                       \
            bufA[U] = base[tp_ * (CS / 4) + roff];                            \
            bufB[U] = base[tp_ * (CS / 4) + roff + 1];                        \
        }                                                                     \
        float llv[8] = {lo.x, lo.y, lo.z, lo.w, hi.x, hi.y, hi.z, hi.w};      \
        float prevv = __shfl_up_sync(0xffffffffu, p[7], 1);                   \
        if (L == 0) prevv = NEGF;                                             \
        unsigned bits = 0;                                                    \
        _Pragma("unroll")                                                     \
        for (int k = 0; k < 8; k++) {                                         \
            float cur = p[k];                                                 \
            bits |= (cur >= prevv ? 1u : 0u) << k;                            \
            float m  = fmaxf(cur, prevv);                                     \
            float nn = __fadd_rn(m, llv[k]);                                  \
            p[k] = MASKED ? ((((L << 3) + k) <= t_) ? nn : NEGF) : nn;        \
            prevv = cur;                                                      \
        }                                                                     \
        sdir[t_ * 32 + L] = (unsigned char)bits;                              \
    }

    for (int t0 = 0; t0 < 256; t0 += 8) {
        int cn = (t0 + 15) >> 6;
        WAITCH(cn)
        BSTEP(t0 + 0, 0, true) BSTEP(t0 + 1, 1, true)
        BSTEP(t0 + 2, 2, true) BSTEP(t0 + 3, 3, true)
        BSTEP(t0 + 4, 4, true) BSTEP(t0 + 5, 5, true)
        BSTEP(t0 + 6, 6, true) BSTEP(t0 + 7, 7, true)
    }
    for (int t0 = 256; t0 < ml_b; t0 += 8) {     // rows >= mellen are masked
        int cn = (t0 + 15) >> 6; if (cn > 15) cn = 15;
        WAITCH(cn)
        BSTEP(t0 + 0, 0, false) BSTEP(t0 + 1, 1, false)
        BSTEP(t0 + 2, 2, false) BSTEP(t0 + 3, 3, false)
        BSTEP(t0 + 4, 4, false) BSTEP(t0 + 5, 5, false)
        BSTEP(t0 + 6, 6, false) BSTEP(t0 + 7, 7, false)
    }
#undef BSTEP
#undef WAITCH

    __syncwarp();

    // Backtrack. Reference forces dir=1 wherever attnmask==0, so for
    // t >= mellen the index stays pinned at textlen-1; inside the mask the
    // traced path never enters s >= textlen, so raw mk bits are correct.
    // De-chained in groups of 4 rows: index span <= 4 => 2 candidate bytes.
    if (L == 0) {
        int* gout = g_idx + b * CT;
        int idx = tl_b - 1;
        int t = CT - 1;
        for (; t >= ml_b; --t) gout[t] = idx;
        while (t >= 3) {
            int A  = idx >> 3;
            int Bq = ((idx >= 3) ? (idx - 3) : 0) >> 3;
            unsigned hi0 = sdir[t * 32 + A];
            unsigned hi1 = sdir[(t - 1) * 32 + A], lo1 = sdir[(t - 1) * 32 + Bq];
            unsigned hi2 = sdir[(t - 2) * 32 + A], lo2 = sdir[(t - 2) * 32 + Bq];
            unsigned hi3 = sdir[(t - 3) * 32 + A], lo3 = sdir[(t - 3) * 32 + Bq];
            gout[t] = idx;
            idx += (int)((hi0 >> (idx & 7)) & 1u) - 1;
            gout[t - 1] = idx;
            unsigned wd = ((idx >> 3) == A) ? hi1 : lo1;
            idx += (int)((wd >> (idx & 7)) & 1u) - 1;
            gout[t - 2] = idx;
            wd = ((idx >> 3) == A) ? hi2 : lo2;
            idx += (int)((wd >> (idx & 7)) & 1u) - 1;
            gout[t - 3] = idx;
            wd = ((idx >> 3) == A) ? hi3 : lo3;
            idx += (int)((wd >> (idx & 7)) & 1u) - 1;
            t -= 4;
        }
        for (; t >= 0; --t) {
            gout[t] = idx;
            idx += (int)((sdir[t * 32 + (idx >> 3)] >> (idx & 7)) & 1u) - 1;
        }
    }
}

// ---------------------------------------------------------------------------
// Kernel C: write residual [B,T,N] then attn [B,T,S] into d_out (float4).
// Also re-zeroes g_flag for the NEXT launch (stream-ordered after all flag
// use; flags are zero-initialized at module load for the first call).
// ---------------------------------------------------------------------------
__global__ __launch_bounds__(256)
void kernelC(const float* __restrict__ latent, const float* __restrict__ mean,
             const int* __restrict__ mellen, float* __restrict__ out)
{
    if (blockIdx.x == 0 && threadIdx.x < CB * 16)
        g_flag[threadIdx.x] = 0;

    const int RES4 = CB * CT * CN / 4;           // 655360
    const int TOT4 = RES4 + CB * CT * CS / 4;    // 2752512
    int i = blockIdx.x * blockDim.x + threadIdx.x;
    if (i >= TOT4) return;
    float4* out4 = (float4*)out;

    if (i < RES4) {
        int f  = i << 2;
        int bt = f / CN;
        int n  = f - bt * CN;
        int b  = bt >> 10;
        int t  = bt & (CT - 1);
        float4 r = ((const float4*)latent)[i];
        if (t < __ldg(&mellen[b])) {
            int sidx = g_idx[bt];
            float4 mv = *(const float4*)(mean + ((size_t)(b * CS + sidx)) * CN + n);
            r.x -= mv.x; r.y -= mv.y; r.z -= mv.z; r.w -= mv.w;
        }
        out4[i] = r;
    } else {
        int f  = (i - RES4) << 2;
        int bt = f >> 8;                 // / CS
        int s0 = f & (CS - 1);
        int b  = bt >> 10;
        int t  = bt & (CT - 1);
        float4 v = make_float4(0.f, 0.f, 0.f, 0.f);
        if (t < __ldg(&mellen[b])) {
            int sidx = g_idx[bt];        // always < textlen[b] => textmask == 1
            v.x = (sidx == s0)     ? 1.f : 0.f;
            v.y = (sidx == s0 + 1) ? 1.f : 0.f;
            v.z = (sidx == s0 + 2) ? 1.f : 0.f;
            v.w = (sidx == s0 + 3) ? 1.f : 0.f;
        }
        out4[i] = v;
    }
}

extern "C" void kernel_launch(void* const* d_in, const int* in_sizes, int n_in,
                              void* d_out, int out_size)
{
    const float* latent  = (const float*)d_in[0];   // [32,1024,80]
    const float* mean    = (const float*)d_in[1];   // [32,256,80]
    const int*   textlen = (const int*)d_in[2];     // [32]
    const int*   mellen  = (const int*)d_in[3];     // [32]
    float* out = (float*)d_out;                     // residual (B*T*N) ++ attn (B*T*S)

    const size_t shA = (size_t)(CN * 129 + CN * 65 + 128 + 64) * sizeof(float);
    cudaFuncSetAttribute(kernelAB, cudaFuncAttributeMaxDynamicSharedMemorySize, (int)shA);

    kernelAB<<<32 + CB * 32, 256, shA>>>(latent, mean, textlen, mellen);

    const int TOT4 = (CB * CT * CN + CB * CT * CS) / 4;
    kernelC<<<(TOT4 + 255) / 256, 256>>>(latent, mean, mellen, out);
}